// round 6
// baseline (speedup 1.0000x reference)
#include <cuda_runtime.h>
#include <cstdint>

// ---------------- problem-size constants (dataset: N=100000, E=1600000, D=64) ----
#define MAXN 100000
#define DD   64
#define DD2  128

// ---------------- scratch (static __device__ globals; no allocation) -------------
__device__ float g_agg[(size_t)MAXN * DD];     // 25.6 MB  segment sums
__device__ float g_deg[MAXN];                  // degrees (float)
__device__ float g_t1[(size_t)MAXN * DD2];     // 51.2 MB  pre-BN GEMM1 output
__device__ float g_sum1[DD2], g_sumsq1[DD2];
__device__ float g_sum2[DD],  g_sumsq2[DD];

// ---------------- f32x2 helpers ---------------------------------------------------
__device__ __forceinline__ unsigned long long pack2(float lo, float hi) {
    unsigned long long r;
    asm("mov.b64 %0, {%1,%2};" : "=l"(r) : "f"(lo), "f"(hi));
    return r;
}
__device__ __forceinline__ void unpack2(unsigned long long v, float& lo, float& hi) {
    asm("mov.b64 {%0,%1}, %2;" : "=f"(lo), "=f"(hi) : "l"(v));
}
#define FMA2(acc, a, b) asm("fma.rn.f32x2 %0, %1, %2, %0;" : "+l"(acc) : "l"(a), "l"(b))

// ---------------- kernel 0: zero scratch ------------------------------------------
__global__ void zero_kernel(int n) {
    int stride = gridDim.x * blockDim.x;
    int i = blockIdx.x * blockDim.x + threadIdx.x;
    int total = n * DD;
    for (int idx = i; idx < total; idx += stride) g_agg[idx] = 0.0f;
    for (int idx = i; idx < n; idx += stride)     g_deg[idx] = 0.0f;
    if (i < DD2) { g_sum1[i] = 0.0f; g_sumsq1[i] = 0.0f; }
    if (i < DD)  { g_sum2[i] = 0.0f; g_sumsq2[i] = 0.0f; }
}

// ---------------- kernel 1: edge gather + scatter (16 threads / edge, float4) -----
__global__ void __launch_bounds__(256) edge_kernel(
    const float4* __restrict__ nf, const float4* __restrict__ ef,
    const int* __restrict__ src, const int* __restrict__ dst, int E)
{
    int t = blockIdx.x * blockDim.x + threadIdx.x;
    int e = t >> 4;
    int q = t & 15;
    if (e >= E) return;
    int s = __ldg(src + e);
    int d = __ldg(dst + e);
    float4 a = __ldg(nf + (size_t)s * 16 + q);
    float4 b = __ldcs(ef + (size_t)e * 16 + q);
    float4 v = make_float4(a.x + b.x, a.y + b.y, a.z + b.z, a.w + b.w);
    atomicAdd(reinterpret_cast<float4*>(g_agg) + (size_t)d * 16 + q, v);
    if (q == 0) atomicAdd(&g_deg[d], 1.0f);
}

// ---------------- kernel 2: combine + GEMM1 (tile 128x128, K=64, 512 thr) ---------
// warp tile 32x32; lane: 4 row-pairs x 4 cols. Per k: 2 LDS.128(h) + 1 LDS.128(w)
// + 4 pack2 + 16 FMA2.  acc = 32 regs.
#define HT1 132   // 128 rows + 4 pad (k-major stride, 528B = 16B aligned)
__global__ void __launch_bounds__(512, 2) gemm1_kernel(
    const float* __restrict__ nf, const float* __restrict__ eps,
    const float* __restrict__ W1, const float* __restrict__ b1, int N)
{
    extern __shared__ float sm[];
    float* hs = sm;                       // [64 k][HT1 rows]
    float* ws = sm + 64 * HT1;            // [64 k][128 cols]
    __shared__ float s_sum[DD2], s_sumsq[DD2];

    int tid = threadIdx.x;
    int r0  = blockIdx.x * 128;
    if (tid < DD2) { s_sum[tid] = 0.0f; s_sumsq[tid] = 0.0f; }
    float epsv = 1.0f + eps[0];

    // load W1 (64x128 row-major = k-major already)
    for (int idx = tid; idx < (64 * 128) / 4; idx += 512)
        reinterpret_cast<float4*>(ws)[idx] = reinterpret_cast<const float4*>(W1)[idx];

    // build h = (1+eps)*node + agg/max(deg,1), transposed (k-major)
    for (int c = tid; c < 128 * 16; c += 512) {
        int row = c & 127;
        int kc  = (c >> 7) << 2;     // 0,4,...,60
        int rg  = r0 + row;
        float4 v = make_float4(0.f, 0.f, 0.f, 0.f);
        if (rg < N) {
            float4 a = *reinterpret_cast<const float4*>(nf + (size_t)rg * DD + kc);
            float4 g = *reinterpret_cast<const float4*>(g_agg + (size_t)rg * DD + kc);
            float rd = 1.0f / fmaxf(g_deg[rg], 1.0f);
            v.x = epsv * a.x + g.x * rd;
            v.y = epsv * a.y + g.y * rd;
            v.z = epsv * a.z + g.z * rd;
            v.w = epsv * a.w + g.w * rd;
        }
        hs[(kc + 0) * HT1 + row] = v.x;
        hs[(kc + 1) * HT1 + row] = v.y;
        hs[(kc + 2) * HT1 + row] = v.z;
        hs[(kc + 3) * HT1 + row] = v.w;
    }
    __syncthreads();

    // warp tiling: 16 warps = 4x4 grid of 32x32 warp tiles
    int w    = tid >> 5;
    int lane = tid & 31;
    int wr   = (w & 3) * 32;         // warp row base
    int wc   = (w >> 2) * 32;        // warp col base
    int lr   = (lane & 3) * 8;       // lane row offset (8 rows)
    int lc   = (lane >> 2) * 4;      // lane col offset (4 cols)
    int row0 = wr + lr;
    int col0 = wc + lc;

    unsigned long long acc[4][4];    // [row-pair][col]
#pragma unroll
    for (int i = 0; i < 4; i++)
#pragma unroll
        for (int j = 0; j < 4; j++) acc[i][j] = 0ull;

    const float* hp = hs + row0;
    const float* wp = ws + col0;

#pragma unroll 8
    for (int k = 0; k < 64; k++) {
        ulonglong2 hA = *reinterpret_cast<const ulonglong2*>(hp + k * HT1);      // rows 0-3 (2 pairs)
        ulonglong2 hB = *reinterpret_cast<const ulonglong2*>(hp + k * HT1 + 4);  // rows 4-7
        float4 wv = *reinterpret_cast<const float4*>(wp + k * 128);
        unsigned long long w0 = pack2(wv.x, wv.x);
        unsigned long long w1 = pack2(wv.y, wv.y);
        unsigned long long w2 = pack2(wv.z, wv.z);
        unsigned long long w3 = pack2(wv.w, wv.w);
        FMA2(acc[0][0], hA.x, w0); FMA2(acc[0][1], hA.x, w1);
        FMA2(acc[0][2], hA.x, w2); FMA2(acc[0][3], hA.x, w3);
        FMA2(acc[1][0], hA.y, w0); FMA2(acc[1][1], hA.y, w1);
        FMA2(acc[1][2], hA.y, w2); FMA2(acc[1][3], hA.y, w3);
        FMA2(acc[2][0], hB.x, w0); FMA2(acc[2][1], hB.x, w1);
        FMA2(acc[2][2], hB.x, w2); FMA2(acc[2][3], hB.x, w3);
        FMA2(acc[3][0], hB.y, w0); FMA2(acc[3][1], hB.y, w1);
        FMA2(acc[3][2], hB.y, w2); FMA2(acc[3][3], hB.y, w3);
    }

    // epilogue: +bias, store pre-BN z to g_t1, accumulate column stats
    float bb[4];
#pragma unroll
    for (int j = 0; j < 4; j++) bb[j] = __ldg(b1 + col0 + j);
    float csum[4], csq[4];
#pragma unroll
    for (int j = 0; j < 4; j++) { csum[j] = 0.f; csq[j] = 0.f; }

#pragma unroll
    for (int rp = 0; rp < 4; rp++) {
        float zlo[4], zhi[4];
#pragma unroll
        for (int j = 0; j < 4; j++) unpack2(acc[rp][j], zlo[j], zhi[j]);
        int rlo = r0 + row0 + rp * 2;
        if (rlo < N) {
#pragma unroll
            for (int j = 0; j < 4; j++) {
                zlo[j] += bb[j];
                csum[j] += zlo[j]; csq[j] += zlo[j] * zlo[j];
            }
            *reinterpret_cast<float4*>(g_t1 + (size_t)rlo * DD2 + col0) =
                make_float4(zlo[0], zlo[1], zlo[2], zlo[3]);
        }
        if (rlo + 1 < N) {
#pragma unroll
            for (int j = 0; j < 4; j++) {
                zhi[j] += bb[j];
                csum[j] += zhi[j]; csq[j] += zhi[j] * zhi[j];
            }
            *reinterpret_cast<float4*>(g_t1 + (size_t)(rlo + 1) * DD2 + col0) =
                make_float4(zhi[0], zhi[1], zhi[2], zhi[3]);
        }
    }
#pragma unroll
    for (int j = 0; j < 4; j++) {
        atomicAdd(&s_sum[col0 + j], csum[j]);
        atomicAdd(&s_sumsq[col0 + j], csq[j]);
    }
    __syncthreads();
    if (tid < DD2) {
        atomicAdd(&g_sum1[tid], s_sum[tid]);
        atomicAdd(&g_sumsq1[tid], s_sumsq[tid]);
    }
}

// ---------------- kernel 3: BN1+ReLU + GEMM2 (tile 128x64, K=128 in 2 halves) -----
// 256 thr = 8 warps = 4x2 grid of 32x32 warp tiles; xs AND ws loaded per K-half
// -> smem 50KB -> 4 blocks/SM.
#define XT1 132
__global__ void __launch_bounds__(256, 4) gemm2_kernel(
    const float* __restrict__ W2, const float* __restrict__ b2,
    const float* __restrict__ gamma1, const float* __restrict__ beta1,
    float* __restrict__ out, int N, float invN)
{
    extern __shared__ float sm[];
    float* xs = sm;                        // [64 k][XT1 rows] (per K-half)
    float* ws = sm + 64 * XT1;             // [64 k][64 cols]  (per K-half)
    __shared__ float s_sum[DD], s_sumsq[DD];
    __shared__ float s_scale1[DD2], s_shift1[DD2];

    int tid = threadIdx.x;
    int r0  = blockIdx.x * 128;
    if (tid < DD) { s_sum[tid] = 0.0f; s_sumsq[tid] = 0.0f; }

    // BN1 finalize (folded, per-block redundant)
    if (tid < DD2) {
        float m = g_sum1[tid] * invN;
        float v = fmaxf(g_sumsq1[tid] * invN - m * m, 0.0f);
        float sc = __ldg(gamma1 + tid) * rsqrtf(v + 1e-5f);
        s_scale1[tid] = sc;
        s_shift1[tid] = __ldg(beta1 + tid) - m * sc;
    }

    int w    = tid >> 5;
    int lane = tid & 31;
    int wr   = (w & 3) * 32;
    int wc   = (w >> 2) * 32;        // 0 or 32
    int lr   = (lane & 3) * 8;
    int lc   = (lane >> 2) * 4;
    int row0 = wr + lr;
    int col0 = wc + lc;

    unsigned long long acc[4][4];
#pragma unroll
    for (int i = 0; i < 4; i++)
#pragma unroll
        for (int j = 0; j < 4; j++) acc[i][j] = 0ull;

    const float* hp = xs + row0;
    const float* wp = ws + col0;

#pragma unroll
    for (int kh = 0; kh < 2; kh++) {
        __syncthreads();   // covers s_scale1 on first pass; tile reuse on second

        // load W2 half: rows [kh*64, kh*64+64) of 128x64
        for (int idx = tid; idx < (64 * 64) / 4; idx += 256)
            reinterpret_cast<float4*>(ws)[idx] =
                reinterpret_cast<const float4*>(W2)[kh * 1024 + idx];

        // build x = relu(BN1(z1)) for k in [kh*64, kh*64+64), transposed
        for (int c = tid; c < 128 * 16; c += 256) {
            int row = c & 127;
            int kl  = (c >> 7) << 2;
            int kc  = kh * 64 + kl;
            int rg  = r0 + row;
            float4 v = make_float4(0.f, 0.f, 0.f, 0.f);
            if (rg < N) {
                float4 z = *reinterpret_cast<const float4*>(g_t1 + (size_t)rg * DD2 + kc);
                v.x = fmaxf(fmaf(z.x, s_scale1[kc + 0], s_shift1[kc + 0]), 0.f);
                v.y = fmaxf(fmaf(z.y, s_scale1[kc + 1], s_shift1[kc + 1]), 0.f);
                v.z = fmaxf(fmaf(z.z, s_scale1[kc + 2], s_shift1[kc + 2]), 0.f);
                v.w = fmaxf(fmaf(z.w, s_scale1[kc + 3], s_shift1[kc + 3]), 0.f);
            }
            xs[(kl + 0) * XT1 + row] = v.x;
            xs[(kl + 1) * XT1 + row] = v.y;
            xs[(kl + 2) * XT1 + row] = v.z;
            xs[(kl + 3) * XT1 + row] = v.w;
        }
        __syncthreads();

#pragma unroll 8
        for (int k = 0; k < 64; k++) {
            ulonglong2 hA = *reinterpret_cast<const ulonglong2*>(hp + k * XT1);
            ulonglong2 hB = *reinterpret_cast<const ulonglong2*>(hp + k * XT1 + 4);
            float4 wv = *reinterpret_cast<const float4*>(wp + k * 64);
            unsigned long long w0 = pack2(wv.x, wv.x);
            unsigned long long w1 = pack2(wv.y, wv.y);
            unsigned long long w2 = pack2(wv.z, wv.z);
            unsigned long long w3 = pack2(wv.w, wv.w);
            FMA2(acc[0][0], hA.x, w0); FMA2(acc[0][1], hA.x, w1);
            FMA2(acc[0][2], hA.x, w2); FMA2(acc[0][3], hA.x, w3);
            FMA2(acc[1][0], hA.y, w0); FMA2(acc[1][1], hA.y, w1);
            FMA2(acc[1][2], hA.y, w2); FMA2(acc[1][3], hA.y, w3);
            FMA2(acc[2][0], hB.x, w0); FMA2(acc[2][1], hB.x, w1);
            FMA2(acc[2][2], hB.x, w2); FMA2(acc[2][3], hB.x, w3);
            FMA2(acc[3][0], hB.y, w0); FMA2(acc[3][1], hB.y, w1);
            FMA2(acc[3][2], hB.y, w2); FMA2(acc[3][3], hB.y, w3);
        }
    }

    float bb[4];
#pragma unroll
    for (int j = 0; j < 4; j++) bb[j] = __ldg(b2 + col0 + j);
    float csum[4], csq[4];
#pragma unroll
    for (int j = 0; j < 4; j++) { csum[j] = 0.f; csq[j] = 0.f; }

#pragma unroll
    for (int rp = 0; rp < 4; rp++) {
        float zlo[4], zhi[4];
#pragma unroll
        for (int j = 0; j < 4; j++) unpack2(acc[rp][j], zlo[j], zhi[j]);
        int rlo = r0 + row0 + rp * 2;
        if (rlo < N) {
#pragma unroll
            for (int j = 0; j < 4; j++) {
                zlo[j] += bb[j];
                csum[j] += zlo[j]; csq[j] += zlo[j] * zlo[j];
            }
            *reinterpret_cast<float4*>(out + (size_t)rlo * DD + col0) =
                make_float4(zlo[0], zlo[1], zlo[2], zlo[3]);
        }
        if (rlo + 1 < N) {
#pragma unroll
            for (int j = 0; j < 4; j++) {
                zhi[j] += bb[j];
                csum[j] += zhi[j]; csq[j] += zhi[j] * zhi[j];
            }
            *reinterpret_cast<float4*>(out + (size_t)(rlo + 1) * DD + col0) =
                make_float4(zhi[0], zhi[1], zhi[2], zhi[3]);
        }
    }
#pragma unroll
    for (int j = 0; j < 4; j++) {
        atomicAdd(&s_sum[col0 + j], csum[j]);
        atomicAdd(&s_sumsq[col0 + j], csq[j]);
    }
    __syncthreads();
    if (tid < DD) {
        atomicAdd(&g_sum2[tid], s_sum[tid]);
        atomicAdd(&g_sumsq2[tid], s_sumsq[tid]);
    }
}

// ---------------- kernel 4: BN2 finalize (folded) + BN2 + ReLU in place -----------
__global__ void __launch_bounds__(256) bn2_kernel(
    float* __restrict__ out, const float* __restrict__ gamma2,
    const float* __restrict__ beta2, int N, float invN)
{
    __shared__ float s_scale2[DD], s_shift2[DD];
    int tid = threadIdx.x;
    if (tid < DD) {
        float m = g_sum2[tid] * invN;
        float v = fmaxf(g_sumsq2[tid] * invN - m * m, 0.0f);
        float sc = __ldg(gamma2 + tid) * rsqrtf(v + 1e-5f);
        s_scale2[tid] = sc;
        s_shift2[tid] = __ldg(beta2 + tid) - m * sc;
    }
    __syncthreads();

    int idx = blockIdx.x * blockDim.x + tid;
    int total = N * 16;  // float4 chunks
    if (idx >= total) return;
    int c = (idx & 15) << 2;
    float4 z = reinterpret_cast<float4*>(out)[idx];
    z.x = fmaxf(fmaf(z.x, s_scale2[c + 0], s_shift2[c + 0]), 0.f);
    z.y = fmaxf(fmaf(z.y, s_scale2[c + 1], s_shift2[c + 1]), 0.f);
    z.z = fmaxf(fmaf(z.z, s_scale2[c + 2], s_shift2[c + 2]), 0.f);
    z.w = fmaxf(fmaf(z.w, s_scale2[c + 3], s_shift2[c + 3]), 0.f);
    reinterpret_cast<float4*>(out)[idx] = z;
}

// ---------------- launch -----------------------------------------------------------
extern "C" void kernel_launch(void* const* d_in, const int* in_sizes, int n_in,
                              void* d_out, int out_size) {
    const float* node_feats = (const float*)d_in[0];
    const float* edge_feats = (const float*)d_in[1];
    const int*   src        = (const int*)d_in[2];
    const int*   dst        = (const int*)d_in[3];
    const float* eps        = (const float*)d_in[4];
    const float* W1         = (const float*)d_in[5];
    const float* b1         = (const float*)d_in[6];
    const float* gamma1     = (const float*)d_in[7];
    const float* beta1      = (const float*)d_in[8];
    const float* W2         = (const float*)d_in[9];
    const float* b2         = (const float*)d_in[10];
    const float* gamma2     = (const float*)d_in[11];
    const float* beta2      = (const float*)d_in[12];
    float* out = (float*)d_out;

    int N = in_sizes[0] / DD;
    int E = in_sizes[1] / DD;
    float invN = 1.0f / (float)N;

    size_t sm1 = (size_t)(64 * HT1 + 64 * 128) * sizeof(float);    // ~66 KB
    size_t sm2 = (size_t)(64 * XT1 + 64 * 64) * sizeof(float);     // ~50 KB
    cudaFuncSetAttribute(gemm1_kernel, cudaFuncAttributeMaxDynamicSharedMemorySize, (int)sm1);
    cudaFuncSetAttribute(gemm2_kernel, cudaFuncAttributeMaxDynamicSharedMemorySize, (int)sm2);

    zero_kernel<<<4096, 256>>>(N);
    edge_kernel<<<(E * 16 + 255) / 256, 256>>>(
        (const float4*)node_feats, (const float4*)edge_feats, src, dst, E);

    int nblk = (N + 127) / 128;
    gemm1_kernel<<<nblk, 512, sm1>>>(node_feats, eps, W1, b1, N);
    gemm2_kernel<<<nblk, 256, sm2>>>(W2, b2, gamma1, beta1, out, N, invN);
    bn2_kernel<<<(N * 16 + 255) / 256, 256>>>(out, gamma2, beta2, N, invN);
}